// round 4
// baseline (speedup 1.0000x reference)
#include <cuda_runtime.h>

#define RMAX 32
#define SMAX 2
#define CZ   128               // channels
#define NPOS 66                // 2*(RMAX+1)
#define NU   132               // combined pos/tok table rows
#define NROW 138               // NU + 6 chain rows
#define NMAX 1024

// Folded tables in shared:
//   U[d]    (d<66) = W_pos[d] + W_tok[65]   (same_chain, !same_res -> index d_res)
//   U[66+d] (d<66) = W_tok[d] + W_pos[32]   (same_chain,  same_res -> index 66+d_tok)
//   (!same_chain -> U[65] = W_pos[65] + W_tok[65])
//   C[d]    (d<6)  = W_ch[d] + (d<5 ? w_ent : 0)
__global__ __launch_bounds__(1024, 2)
void relpos_kernel(const int* __restrict__ asym,
                   const int* __restrict__ resi,
                   const int* __restrict__ ent,
                   const int* __restrict__ sym,
                   const int* __restrict__ tok,
                   const float* __restrict__ W,
                   float* __restrict__ out,
                   int N)
{
    extern __shared__ float smem[];
    float* sW   = smem;                        // [NROW*CZ]
    int*   sIdx = (int*)(smem + NROW * CZ);    // [2][NMAX] double-buffered

    const int tid = threadIdx.x;

    // Stage folded tables into shared (once per CTA).
    for (int k = tid; k < NROW * CZ; k += blockDim.x) {
        int row = k >> 7;            // /CZ
        int c   = k & (CZ - 1);
        float v;
        if (row < NPOS) {
            v = W[row * CZ + c] + W[(NPOS + 65) * CZ + c];
        } else if (row < NU) {
            v = W[(NPOS + (row - NPOS)) * CZ + c] + W[32 * CZ + c];
        } else {
            int d = row - NU;
            v = W[(2 * NPOS + 1 + d) * CZ + c];
            if (d < 5) v += W[(2 * NPOS) * CZ + c];
        }
        sW[k] = v;
    }

    // Thread tid owns column j = tid: keep its quintuple in registers.
    int aj = 0, rj = 0, ej = 0, sj = 0, tj = 0;
    if (tid < N) {
        aj = asym[tid]; rj = resi[tid]; ej = ent[tid];
        sj = sym[tid];  tj = tok[tid];
    }

    const float4* sW4  = (const float4*)sW;
    float4*       out4 = (float4*)out;
    const int tx = tid & 31;           // channel group: c = tx*4 .. tx*4+3
    const int ty = tid >> 5;           // warp id
    const int chunk = (N + 31) >> 5;   // contiguous j-range per warp
    const int jbeg = ty * chunk;
    const int jend = (jbeg + chunk) < N ? (jbeg + chunk) : N;

    // Memoized lookup: valid across rows too (sW is constant).
    int pprev = -1;
    float4 s = make_float4(0.f, 0.f, 0.f, 0.f);

    int it = 0;
    for (int i = blockIdx.x; i < N; i += gridDim.x, ++it) {
        const int ai = __ldg(&asym[i]), ri = __ldg(&resi[i]);
        const int ei = __ldg(&ent[i]),  si = __ldg(&sym[i]);
        const int ti = __ldg(&tok[i]);

        int* sI = sIdx + (it & 1) * NMAX;
        if (tid < N) {
            bool sc = (ai == aj);
            bool sr = (ri == rj);
            bool se = (ei == ej);

            int u;
            if (sc && sr)  u = NPOS + min(max(ti - tj + RMAX, 0), 2 * RMAX);
            else if (sc)   u = min(max(ri - rj + RMAX, 0), 2 * RMAX);
            else           u = 2 * RMAX + 1;

            int cRel = se ? min(max(si - sj + SMAX, 0), 2 * SMAX) : (2 * SMAX + 1);
            sI[tid] = u | (cRel << 8);
        }
        __syncthreads();   // sI ready; also guards prev-buffer reuse 2 iters later

        const size_t rowbase = (size_t)i * N;
        #pragma unroll 4
        for (int j = jbeg; j < jend; ++j) {
            int p = sI[j];                     // warp-uniform broadcast
            if (p != pprev) {                  // warp-uniform branch
                pprev = p;
                int rU = p & 0xFF;
                int rC = NU + (p >> 8);
                float4 a = sW4[rU * (CZ / 4) + tx];
                float4 c = sW4[rC * (CZ / 4) + tx];
                s.x = a.x + c.x;
                s.y = a.y + c.y;
                s.z = a.z + c.z;
                s.w = a.w + c.w;
            }
            __stcs(&out4[(rowbase + j) * (CZ / 4) + tx], s);
        }
    }
}

extern "C" void kernel_launch(void* const* d_in, const int* in_sizes, int n_in,
                              void* d_out, int out_size)
{
    const int*   asym = (const int*)d_in[0];
    const int*   resi = (const int*)d_in[1];
    const int*   ent  = (const int*)d_in[2];
    const int*   sym  = (const int*)d_in[3];
    const int*   tok  = (const int*)d_in[4];
    const float* W    = (const float*)d_in[5];
    float*       out  = (float*)d_out;

    const int N = in_sizes[0];                  // B*N with B==1 -> 1024

    int nsm = 148;
    cudaDeviceGetAttribute(&nsm, cudaDevAttrMultiProcessorCount, 0);
    int grid = 2 * nsm;
    if (grid > N) grid = N;

    const int smem_bytes = NROW * CZ * (int)sizeof(float)
                         + 2 * NMAX * (int)sizeof(int);

    cudaFuncSetAttribute(relpos_kernel,
                         cudaFuncAttributeMaxDynamicSharedMemorySize, smem_bytes);

    relpos_kernel<<<grid, 1024, smem_bytes>>>(asym, resi, ent, sym, tok, W, out, N);
}

// round 5
// speedup vs baseline: 1.0225x; 1.0225x over previous
#include <cuda_runtime.h>

#define RMAX 32
#define SMAX 2
#define CZ   128               // channels
#define NPOS 66                // 2*(RMAX+1)
#define NU   132               // combined pos/tok table rows
#define NROW 138               // NU + 6 chain rows
#define NMAX 1024
#define HALF 512               // columns per work unit

// Folded tables in shared:
//   U[d]    (d<66) = W_pos[d] + W_tok[65]   (same_chain, !same_res -> index d_res)
//   U[66+d] (d<66) = W_tok[d] + W_pos[32]   (same_chain,  same_res -> index 66+d_tok)
//   (!same_chain -> U[65] = W_pos[65] + W_tok[65])
//   C[d]    (d<6)  = W_ch[d] + (d<5 ? w_ent : 0)
__global__ __launch_bounds__(1024, 2)
void relpos_kernel(const int* __restrict__ asym,
                   const int* __restrict__ resi,
                   const int* __restrict__ ent,
                   const int* __restrict__ sym,
                   const int* __restrict__ tok,
                   const float* __restrict__ W,
                   float* __restrict__ out,
                   int N)
{
    extern __shared__ float smem[];
    float* sW   = smem;                        // [NROW*CZ]
    int*   sIdx = (int*)(smem + NROW * CZ);    // [2][HALF] double-buffered

    const int tid = threadIdx.x;

    // Stage folded tables into shared (once per CTA).
    for (int k = tid; k < NROW * CZ; k += blockDim.x) {
        int row = k >> 7;            // /CZ
        int c   = k & (CZ - 1);
        float v;
        if (row < NPOS) {
            v = W[row * CZ + c] + W[(NPOS + 65) * CZ + c];
        } else if (row < NU) {
            v = W[(NPOS + (row - NPOS)) * CZ + c] + W[32 * CZ + c];
        } else {
            int d = row - NU;
            v = W[(2 * NPOS + 1 + d) * CZ + c];
            if (d < 5) v += W[(2 * NPOS) * CZ + c];
        }
        sW[k] = v;
    }

    // Thread tid owns column j = tid: keep its quintuple in registers.
    int aj = 0, rj = 0, ej = 0, sj = 0, tj = 0;
    if (tid < N) {
        aj = asym[tid]; rj = resi[tid]; ej = ent[tid];
        sj = sym[tid];  tj = tok[tid];
    }

    const float4* sW4  = (const float4*)sW;
    float4*       out4 = (float4*)out;
    const int tx = tid & 31;           // channel group: c = tx*4 .. tx*4+3
    const int ty = tid >> 5;           // warp id (0..31)

    // Memoized lookup: valid across units (sW is constant; p encodes all state).
    int pprev = -1;
    float4 s = make_float4(0.f, 0.f, 0.f, 0.f);

    const int nUnits = 2 * N;          // work unit = half-row (512 columns)
    int it = 0;
    for (int v = blockIdx.x; v < nUnits; v += gridDim.x, ++it) {
        const int i = v >> 1;          // row
        const int h = v & 1;           // which half of the row

        const int ai = __ldg(&asym[i]), ri = __ldg(&resi[i]);
        const int ei = __ldg(&ent[i]),  si = __ldg(&sym[i]);
        const int ti = __ldg(&tok[i]);

        int* sI = sIdx + (it & 1) * HALF;
        // Threads whose owned column lies in this half compute its packed index.
        if ((tid >> 9) == h) {
            bool sc = (ai == aj);
            bool sr = (ri == rj);
            bool se = (ei == ej);

            int u;
            if (sc && sr)  u = NPOS + min(max(ti - tj + RMAX, 0), 2 * RMAX);
            else if (sc)   u = min(max(ri - rj + RMAX, 0), 2 * RMAX);
            else           u = 2 * RMAX + 1;

            int cRel = se ? min(max(si - sj + SMAX, 0), 2 * SMAX) : (2 * SMAX + 1);
            sI[tid & (HALF - 1)] = u | (cRel << 8);
        }
        __syncthreads();   // sI ready; ping-pong guards prev buffer

        // Warp ty handles 16 contiguous columns of this half-row.
        const size_t base = ((size_t)i * N + (size_t)h * HALF) * (CZ / 4);
        const int jb = ty * 16;
        #pragma unroll 8
        for (int q = 0; q < 16; ++q) {
            int p = sI[jb + q];                // warp-uniform broadcast
            if (p != pprev) {                  // warp-uniform branch
                pprev = p;
                int rU = p & 0xFF;
                int rC = NU + (p >> 8);
                float4 a = sW4[rU * (CZ / 4) + tx];
                float4 c = sW4[rC * (CZ / 4) + tx];
                s.x = a.x + c.x;
                s.y = a.y + c.y;
                s.z = a.z + c.z;
                s.w = a.w + c.w;
            }
            __stcs(&out4[base + (size_t)(jb + q) * (CZ / 4) + tx], s);
        }
    }
}

extern "C" void kernel_launch(void* const* d_in, const int* in_sizes, int n_in,
                              void* d_out, int out_size)
{
    const int*   asym = (const int*)d_in[0];
    const int*   resi = (const int*)d_in[1];
    const int*   ent  = (const int*)d_in[2];
    const int*   sym  = (const int*)d_in[3];
    const int*   tok  = (const int*)d_in[4];
    const float* W    = (const float*)d_in[5];
    float*       out  = (float*)d_out;

    const int N = in_sizes[0];                  // B*N with B==1 -> 1024

    int nsm = 148;
    cudaDeviceGetAttribute(&nsm, cudaDevAttrMultiProcessorCount, 0);
    int grid = 2 * nsm;
    if (grid > 2 * N) grid = 2 * N;

    const int smem_bytes = NROW * CZ * (int)sizeof(float)
                         + 2 * HALF * (int)sizeof(int);

    cudaFuncSetAttribute(relpos_kernel,
                         cudaFuncAttributeMaxDynamicSharedMemorySize, smem_bytes);

    relpos_kernel<<<grid, 1024, smem_bytes>>>(asym, resi, ent, sym, tok, W, out, N);
}